// round 8
// baseline (speedup 1.0000x reference)
#include <cuda_runtime.h>
#include <cuda_fp16.h>
#include <math.h>
#include <stdint.h>

#define MTOK 4096   // B*N
#define DDIM 1024
#define NHEAD 16
#define SEQ 2048
#define QSTR 3072   // fused qkv row stride

// ---------------- scratch (device globals; no allocs allowed) ----------------
static __device__ float g_qkv[MTOK * QSTR];      // [q | k | v] fused
static __device__ float g_attn[MTOK * DDIM];
static __device__ float g_gate[MTOK * DDIM];
static __device__ float g_lam[MTOK * NHEAD];
static __device__ float g_gam[MTOK * NHEAD];
static __device__ __half g_xh[MTOK * DDIM];
static __device__ __half g_g1h[MTOK * 64];
static __device__ __half g_normedh[MTOK * DDIM];
static __device__ __half g_wqkvt[3 * DDIM * DDIM];
static __device__ __half g_wot[DDIM * DDIM];
static __device__ __half g_wg1t[64 * DDIM];
static __device__ __half g_wg2t[DDIM * 64];

__device__ __forceinline__ uint32_t smem_u32(const void* p) {
    uint32_t a;
    asm("{ .reg .u64 t; cvta.to.shared.u64 t, %1; cvt.u32.u64 %0, t; }" : "=r"(a) : "l"(p));
    return a;
}
__device__ __forceinline__ void cp16(uint32_t dst, const void* src, int valid) {
    int sz = valid ? 16 : 0;
    asm volatile("cp.async.cg.shared.global [%0], [%1], 16, %2;" :: "r"(dst), "l"(src), "r"(sz));
}
__device__ __forceinline__ void cp4(uint32_t dst, const void* src) {
    asm volatile("cp.async.ca.shared.global [%0], [%1], 4;" :: "r"(dst), "l"(src));
}

// ================= fp16 tensor-core GEMM: C = act(A @ Bt^T) =================
// Tile 128x128, K-tile 32, 4-stage cp.async (2-ahead), 2 CTAs/SM.
#define ROWB 80
#define STAGEB (128 * ROWB * 2)          // 20480
#define HG_SMEM (4 * STAGEB)             // 81920

__global__ __launch_bounds__(256, 2)
void hgemm(const __half* __restrict__ A, const __half* __restrict__ Bt,
           void* __restrict__ Cout, int Ntot, int K, int act, int outHalf)
{
    extern __shared__ __align__(128) char smem[];
    const uint32_t sb = smem_u32(smem);
    const int tid = threadIdx.x, lane = tid & 31, warp = tid >> 5;
    const int wm = warp >> 2, wn = warp & 3;
    const int g = lane >> 2, tig = lane & 3;
    const int m0 = blockIdx.y * 128, n0 = blockIdx.x * 128;
    const int NC = K >> 5;

    float acc[4][4][4];
#pragma unroll
    for (int mt = 0; mt < 4; ++mt)
#pragma unroll
        for (int nt = 0; nt < 4; ++nt)
#pragma unroll
            for (int j = 0; j < 4; ++j) acc[mt][nt][j] = 0.f;

#define LOAD_TILE(kt, ss) do { \
    uint32_t aB = sb + (ss) * STAGEB; \
    uint32_t bB = aB + 128 * ROWB; \
    _Pragma("unroll") \
    for (int i = 0; i < 2; ++i) { \
        int id = tid + i * 256; \
        int r = id >> 2, c = id & 3; \
        cp16(aB + r * ROWB + c * 16, A + (size_t)(m0 + r) * K + (kt) * 32 + c * 8, 1); \
        int nr = n0 + r; int ok = nr < Ntot; int nrc = ok ? nr : 0; \
        cp16(bB + r * ROWB + c * 16, Bt + (size_t)nrc * K + (kt) * 32 + c * 8, ok); \
    } \
} while (0)

#pragma unroll
    for (int p = 0; p < 3; ++p) {
        if (p < NC) LOAD_TILE(p, p);
        asm volatile("cp.async.commit_group;" ::: "memory");
    }

    for (int kt = 0; kt < NC; ++kt) {
        asm volatile("cp.async.wait_group 2;" ::: "memory");
        __syncthreads();
        int ln = kt + 3;
        if (ln < NC) LOAD_TILE(ln, ln & 3);
        asm volatile("cp.async.commit_group;" ::: "memory");

        uint32_t aB = sb + (kt & 3) * STAGEB;
        uint32_t bB = aB + 128 * ROWB;
#pragma unroll
        for (int s = 0; s < 2; ++s) {
            uint32_t af[4][4], bf[4][2];
#pragma unroll
            for (int mt = 0; mt < 4; ++mt) {
                uint32_t addr = aB + (wm * 64 + mt * 16 + (lane & 15)) * ROWB
                              + (2 * s + (lane >> 4)) * 16;
                asm volatile("ldmatrix.sync.aligned.m8n8.x4.shared.b16 {%0,%1,%2,%3}, [%4];"
                    : "=r"(af[mt][0]), "=r"(af[mt][1]), "=r"(af[mt][2]), "=r"(af[mt][3])
                    : "r"(addr));
            }
#pragma unroll
            for (int nt = 0; nt < 4; ++nt) {
                uint32_t addr = bB + (wn * 32 + nt * 8 + (lane & 7)) * ROWB
                              + (2 * s + ((lane >> 3) & 1)) * 16;
                asm volatile("ldmatrix.sync.aligned.m8n8.x2.shared.b16 {%0,%1}, [%2];"
                    : "=r"(bf[nt][0]), "=r"(bf[nt][1]) : "r"(addr));
            }
#pragma unroll
            for (int mt = 0; mt < 4; ++mt)
#pragma unroll
                for (int nt = 0; nt < 4; ++nt) {
                    asm volatile(
                        "mma.sync.aligned.m16n8k16.row.col.f32.f16.f16.f32 "
                        "{%0,%1,%2,%3}, {%4,%5,%6,%7}, {%8,%9}, {%0,%1,%2,%3};"
                        : "+f"(acc[mt][nt][0]), "+f"(acc[mt][nt][1]),
                          "+f"(acc[mt][nt][2]), "+f"(acc[mt][nt][3])
                        : "r"(af[mt][0]), "r"(af[mt][1]), "r"(af[mt][2]), "r"(af[mt][3]),
                          "r"(bf[nt][0]), "r"(bf[nt][1]));
                }
        }
        __syncthreads();
    }
#undef LOAD_TILE

    float* Cf = (float*)Cout;
    __half* Ch = (__half*)Cout;
#pragma unroll
    for (int mt = 0; mt < 4; ++mt) {
        int row = m0 + wm * 64 + mt * 16 + g;
#pragma unroll
        for (int nt = 0; nt < 4; ++nt) {
            int col = n0 + wn * 32 + nt * 8 + tig * 2;
            if (col < Ntot) {
                float c0 = acc[mt][nt][0], c1 = acc[mt][nt][1];
                float c2 = acc[mt][nt][2], c3 = acc[mt][nt][3];
                if (act == 1) {
                    c0 = c0 / (1.f + expf(-c0)); c1 = c1 / (1.f + expf(-c1));
                    c2 = c2 / (1.f + expf(-c2)); c3 = c3 / (1.f + expf(-c3));
                } else if (act == 2) {
                    c0 = 1.f / (1.f + expf(-c0)); c1 = 1.f / (1.f + expf(-c1));
                    c2 = 1.f / (1.f + expf(-c2)); c3 = 1.f / (1.f + expf(-c3));
                }
                if (outHalf) {
                    *(__half2*)&Ch[(size_t)row * Ntot + col]       = __floats2half2_rn(c0, c1);
                    *(__half2*)&Ch[(size_t)(row + 8) * Ntot + col] = __floats2half2_rn(c2, c3);
                } else {
                    *(float2*)&Cf[(size_t)row * Ntot + col]       = make_float2(c0, c1);
                    *(float2*)&Cf[(size_t)(row + 8) * Ntot + col] = make_float2(c2, c3);
                }
            }
        }
    }
}

// ================= fused prep: transposes + f2h + fgamma in ONE launch =================
// blocks [0,4224): weight transpose tiles; [4224,8320): x f32->f16; [8320,8576): fgamma
__global__ void k_prep(const float* __restrict__ x,
                       const float* __restrict__ Wq, const float* __restrict__ Wk,
                       const float* __restrict__ Wv, const float* __restrict__ Wo,
                       const float* __restrict__ Wg1, const float* __restrict__ Wg2,
                       const float* __restrict__ Wf, const float* __restrict__ Wgm,
                       __half* __restrict__ wqkvt, __half* __restrict__ wot,
                       __half* __restrict__ wg1t, __half* __restrict__ wg2t,
                       __half* __restrict__ xh,
                       float* __restrict__ lam, float* __restrict__ gam)
{
    int blk = blockIdx.x;
    int tid = threadIdx.y * 32 + threadIdx.x;
    if (blk < 4224) {
        // ---- transpose+convert ----
        __shared__ float t[32][33];
        const float* S; __half* D; int R, C, tile;
        if (blk < 3072) {
            int seg = blk >> 10; tile = blk & 1023;
            S = (seg == 0) ? Wq : (seg == 1) ? Wk : Wv;
            D = wqkvt + (size_t)seg * DDIM * DDIM; R = DDIM; C = DDIM;
        } else if (blk < 4096) { tile = blk - 3072; S = Wo;  D = wot;  R = DDIM; C = DDIM; }
        else if (blk < 4160)   { tile = blk - 4096; S = Wg1; D = wg1t; R = DDIM; C = 64; }
        else                   { tile = blk - 4160; S = Wg2; D = wg2t; R = 64;   C = DDIM; }
        int tiles_x = C >> 5;
        int c0 = (tile % tiles_x) * 32, r0 = (tile / tiles_x) * 32;
        int xq = threadIdx.x, y = threadIdx.y;
#pragma unroll
        for (int i = 0; i < 32; i += 8) t[y + i][xq] = S[(size_t)(r0 + y + i) * C + c0 + xq];
        __syncthreads();
#pragma unroll
        for (int i = 0; i < 32; i += 8)
            D[(size_t)(c0 + y + i) * R + r0 + xq] = __float2half_rn(t[xq][y + i]);
    } else if (blk < 8320) {
        // ---- x -> half ----
        int i = ((blk - 4224) * 256 + tid) * 4;
        float4 f = *(const float4*)&x[i];
        *(__half2*)&xh[i]     = __floats2half2_rn(f.x, f.y);
        *(__half2*)&xh[i + 2] = __floats2half2_rn(f.z, f.w);
    } else {
        // ---- f/gamma projections: 16 tokens per block ----
        __shared__ float xs[16][33];
        __shared__ float Ws[32][32];
        int t0 = (blk - 8320) * 16;
        int c = tid & 31, tg = tid >> 5;
        float acc[2] = {0.f, 0.f};
        for (int k0 = 0; k0 < DDIM; k0 += 32) {
            __syncthreads();
#pragma unroll
            for (int i = 0; i < 2; ++i) {
                int idx = tid + i * 256;
                int tt = idx >> 5, kk = idx & 31;
                xs[tt][kk] = x[(size_t)(t0 + tt) * DDIM + k0 + kk];
            }
#pragma unroll
            for (int i = 0; i < 4; ++i) {
                int idx = tid + i * 256;
                int kr = idx >> 5, col = idx & 31;
                Ws[kr][col] = (col < 16) ? Wf[(k0 + kr) * NHEAD + col]
                                         : Wgm[(k0 + kr) * NHEAD + (col - 16)];
            }
            __syncthreads();
#pragma unroll 8
            for (int kk = 0; kk < 32; ++kk) {
                float w = Ws[kk][c];
                acc[0] = fmaf(xs[tg * 2][kk], w, acc[0]);
                acc[1] = fmaf(xs[tg * 2 + 1][kk], w, acc[1]);
            }
        }
#pragma unroll
        for (int i = 0; i < 2; ++i) {
            int t = t0 + tg * 2 + i;
            float sg = 1.f / (1.f + expf(-acc[i]));
            if (c < 16) lam[t * NHEAD + c] = sg;
            else        gam[t * NHEAD + (c - 16)] = -sg;
        }
    }
}

// ================= delta-rule scan (fused l2norm + a) =================
// 128 blocks = 32 (b,h) x 4 quarters; 64 thr = 16 cols x 4 subs; 16 state regs.
// Raw k kept in smem. Per token: e = k.s ; u = (l*c*invn)*e + v ;
// s' = l*s + k*(invn*u) ; o = q.s'   (a array eliminated: a = k*invn*c)
__global__ __launch_bounds__(64)
void k_scan(const float* __restrict__ qkv, const float* __restrict__ lamA,
            const float* __restrict__ gamA, float* __restrict__ o)
{
    __shared__ __align__(16) float qs[2][16][64];
    __shared__ __align__(16) float ks[2][16][64];
    __shared__ __align__(16) float vs[2][16][16];
    __shared__ float lmS[2][16], gmS[2][16], f1S[2][16], inS[2][16];

    const int blk = blockIdx.x;           // 0..127
    const int bh = blk >> 2, quarter = blk & 3;
    const int b = bh >> 4, h = bh & 15;
    const int tid = threadIdx.x;          // 0..63
    const int col = tid >> 2;             // 0..15
    const int sub = tid & 3;              // 0..3
    const int tok0 = b * SEQ;
    const int hoff = h * 64;

    const uint32_t qsB = smem_u32(&qs[0][0][0]);
    const uint32_t ksB = smem_u32(&ks[0][0][0]);
    const uint32_t vsB = smem_u32(&vs[0][0][0]);
    const uint32_t lmB = smem_u32(&lmS[0][0]);
    const uint32_t gmB = smem_u32(&gmS[0][0]);

#define SC_LOAD(stg, buf) do { \
    int tb_ = tok0 + (stg) * 16; \
    _Pragma("unroll") \
    for (int i = 0; i < 4; ++i) { \
        int idx = tid + i * 64; \
        int tt = idx >> 4, c4 = idx & 15; \
        uint32_t so = (uint32_t)(((buf) * 16 + tt) * 64 + c4 * 4) * 4; \
        const float* qrow = qkv + (size_t)(tb_ + tt) * QSTR + hoff + c4 * 4; \
        cp16(qsB + so, qrow, 1); \
        cp16(ksB + so, qrow + DDIM, 1); \
    } \
    { \
        int tt = tid >> 2, c4 = tid & 3; \
        uint32_t so = (uint32_t)(((buf) * 16 + tt) * 16 + c4 * 4) * 4; \
        cp16(vsB + so, qkv + (size_t)(tb_ + tt) * QSTR + 2 * DDIM + hoff + quarter * 16 + c4 * 4, 1); \
    } \
    if (tid < 16) \
        cp4(lmB + (uint32_t)((buf) * 16 + tid) * 4, lamA + (size_t)(tb_ + tid) * NHEAD + h); \
    else if (tid < 32) \
        cp4(gmB + (uint32_t)((buf) * 16 + tid - 16) * 4, gamA + (size_t)(tb_ + tid - 16) * NHEAD + h); \
} while (0)

    // per-tile prepass: l2 norms + fused scalars
#define SC_PRE(buf) do { \
    int tt_ = tid >> 2, part_ = tid & 3; \
    const float* kr = &ks[buf][tt_][part_ * 16]; \
    float4 p0 = *(const float4*)kr, p1 = *(const float4*)(kr + 4); \
    float4 p2 = *(const float4*)(kr + 8), p3 = *(const float4*)(kr + 12); \
    float ssum = p0.x*p0.x + p0.y*p0.y + p0.z*p0.z + p0.w*p0.w \
               + p1.x*p1.x + p1.y*p1.y + p1.z*p1.z + p1.w*p1.w \
               + p2.x*p2.x + p2.y*p2.y + p2.z*p2.z + p2.w*p2.w \
               + p3.x*p3.x + p3.y*p3.y + p3.z*p3.z + p3.w*p3.w; \
    ssum += __shfl_xor_sync(0xffffffffu, ssum, 1); \
    ssum += __shfl_xor_sync(0xffffffffu, ssum, 2); \
    if (part_ == 0) { \
        float inv_ = 1.f / fmaxf(sqrtf(ssum), 1e-12f); \
        float l_ = lmS[buf][tt_]; \
        float c_ = gmS[buf][tt_] * l_; \
        inS[buf][tt_] = inv_; \
        f1S[buf][tt_] = l_ * c_ * inv_; \
    } \
} while (0)

    float s[16];
#pragma unroll
    for (int j = 0; j < 16; ++j) s[j] = 0.f;

    SC_LOAD(0, 0);
    asm volatile("cp.async.commit_group;" ::: "memory");
    asm volatile("cp.async.wait_group 0;" ::: "memory");
    __syncthreads();
    SC_PRE(0);
    __syncthreads();

    const int NT = SEQ / 16;
    for (int st = 0; st < NT; ++st) {
        const int buf = st & 1;
        if (st + 1 < NT) SC_LOAD(st + 1, buf ^ 1);
        asm volatile("cp.async.commit_group;" ::: "memory");

        const int tb = tok0 + st * 16;
#pragma unroll 4
        for (int tt = 0; tt < 16; ++tt) {
            float l = lmS[buf][tt];
            float f1 = f1S[buf][tt];
            float inv = inS[buf][tt];
            const float* krow = &ks[buf][tt][sub * 16];
            float4 k0 = *(const float4*)krow;
            float4 k1 = *(const float4*)(krow + 4);
            float4 k2 = *(const float4*)(krow + 8);
            float4 k3 = *(const float4*)(krow + 12);
            float e0 = k0.x * s[0] + k0.y * s[1] + k0.z * s[2] + k0.w * s[3];
            float e1 = k1.x * s[4] + k1.y * s[5] + k1.z * s[6] + k1.w * s[7];
            float e2 = k2.x * s[8] + k2.y * s[9] + k2.z * s[10] + k2.w * s[11];
            float e3 = k3.x * s[12] + k3.y * s[13] + k3.z * s[14] + k3.w * s[15];
            float e = (e0 + e1) + (e2 + e3);
            e += __shfl_xor_sync(0xffffffffu, e, 1);
            e += __shfl_xor_sync(0xffffffffu, e, 2);
            float u = fmaf(f1, e, vs[buf][tt][col]);
            float w = inv * u;
            s[0]  = fmaf(k0.x, w, l * s[0]);  s[1]  = fmaf(k0.y, w, l * s[1]);
            s[2]  = fmaf(k0.z, w, l * s[2]);  s[3]  = fmaf(k0.w, w, l * s[3]);
            s[4]  = fmaf(k1.x, w, l * s[4]);  s[5]  = fmaf(k1.y, w, l * s[5]);
            s[6]  = fmaf(k1.z, w, l * s[6]);  s[7]  = fmaf(k1.w, w, l * s[7]);
            s[8]  = fmaf(k2.x, w, l * s[8]);  s[9]  = fmaf(k2.y, w, l * s[9]);
            s[10] = fmaf(k2.z, w, l * s[10]); s[11] = fmaf(k2.w, w, l * s[11]);
            s[12] = fmaf(k3.x, w, l * s[12]); s[13] = fmaf(k3.y, w, l * s[13]);
            s[14] = fmaf(k3.z, w, l * s[14]); s[15] = fmaf(k3.w, w, l * s[15]);
            const float* qrow = &qs[buf][tt][sub * 16];
            float4 q0 = *(const float4*)qrow;
            float4 q1 = *(const float4*)(qrow + 4);
            float4 q2 = *(const float4*)(qrow + 8);
            float4 q3 = *(const float4*)(qrow + 12);
            float o0 = q0.x * s[0] + q0.y * s[1] + q0.z * s[2] + q0.w * s[3];
            float o1 = q1.x * s[4] + q1.y * s[5] + q1.z * s[6] + q1.w * s[7];
            float o2 = q2.x * s[8] + q2.y * s[9] + q2.z * s[10] + q2.w * s[11];
            float o3 = q3.x * s[12] + q3.y * s[13] + q3.z * s[14] + q3.w * s[15];
            float op = (o0 + o1) + (o2 + o3);
            op += __shfl_xor_sync(0xffffffffu, op, 1);
            op += __shfl_xor_sync(0xffffffffu, op, 2);
            if (sub == 0)
                o[(size_t)(tb + tt) * DDIM + hoff + quarter * 16 + col] = op;
        }
        asm volatile("cp.async.wait_group 0;" ::: "memory");
        __syncthreads();
        if (st + 1 < NT) {
            SC_PRE(buf ^ 1);
            __syncthreads();
        }
    }
#undef SC_LOAD
#undef SC_PRE
}

// ================= gate-multiply + LayerNorm -> half =================
__global__ void k_ln(const float* __restrict__ attn, const float* __restrict__ gate,
                     const float* __restrict__ nw, __half* __restrict__ outh)
{
    __shared__ float red[32];
    int t = blockIdx.x;
    int tid = threadIdx.x;  // 256
    int lane = tid & 31, w = tid >> 5;
    float y[4];
    float sm = 0.f;
#pragma unroll
    for (int i = 0; i < 4; ++i) {
        int j = tid + i * 256;
        y[i] = attn[(size_t)t * DDIM + j] * gate[(size_t)t * DDIM + j];
        sm += y[i];
    }
#pragma unroll
    for (int o = 16; o; o >>= 1) sm += __shfl_xor_sync(0xffffffffu, sm, o);
    if (lane == 0) red[w] = sm;
    __syncthreads();
    if (w == 0) {
        float v2 = (lane < 8) ? red[lane] : 0.f;
#pragma unroll
        for (int o = 4; o; o >>= 1) v2 += __shfl_xor_sync(0xffffffffu, v2, o);
        if (lane == 0) red[0] = v2;
    }
    __syncthreads();
    float mu = red[0] * (1.f / DDIM);
    __syncthreads();
    float vsum = 0.f;
#pragma unroll
    for (int i = 0; i < 4; ++i) { float d = y[i] - mu; vsum += d * d; }
#pragma unroll
    for (int o = 16; o; o >>= 1) vsum += __shfl_xor_sync(0xffffffffu, vsum, o);
    if (lane == 0) red[w] = vsum;
    __syncthreads();
    if (w == 0) {
        float v2 = (lane < 8) ? red[lane] : 0.f;
#pragma unroll
        for (int o = 4; o; o >>= 1) v2 += __shfl_xor_sync(0xffffffffu, v2, o);
        if (lane == 0) red[0] = v2;
    }
    __syncthreads();
    float inv = rsqrtf(red[0] * (1.f / DDIM) + 1e-5f);
#pragma unroll
    for (int i = 0; i < 4; ++i) {
        int j = tid + i * 256;
        outh[(size_t)t * DDIM + j] = __float2half_rn((y[i] - mu) * inv * nw[j]);
    }
}

// ================= launch =================
extern "C" void kernel_launch(void* const* d_in, const int* in_sizes, int n_in,
                              void* d_out, int out_size)
{
    const float* x      = (const float*)d_in[0];
    const float* Wq     = (const float*)d_in[1];
    const float* Wk     = (const float*)d_in[2];
    const float* Wv     = (const float*)d_in[3];
    const float* Wgamma = (const float*)d_in[4];
    const float* Wf     = (const float*)d_in[5];
    const float* Wg1    = (const float*)d_in[6];
    const float* Wg2    = (const float*)d_in[7];
    const float* Wo     = (const float*)d_in[8];
    const float* nw     = (const float*)d_in[9];
    float* out = (float*)d_out;

    float *qkv, *attn, *gate, *lam, *gam;
    __half *xh, *g1h, *normedh, *wqkvt, *wot, *wg1t, *wg2t;
    cudaGetSymbolAddress((void**)&qkv, g_qkv);
    cudaGetSymbolAddress((void**)&attn, g_attn);
    cudaGetSymbolAddress((void**)&gate, g_gate);
    cudaGetSymbolAddress((void**)&lam, g_lam);
    cudaGetSymbolAddress((void**)&gam, g_gam);
    cudaGetSymbolAddress((void**)&xh, g_xh);
    cudaGetSymbolAddress((void**)&g1h, g_g1h);
    cudaGetSymbolAddress((void**)&normedh, g_normedh);
    cudaGetSymbolAddress((void**)&wqkvt, g_wqkvt);
    cudaGetSymbolAddress((void**)&wot, g_wot);
    cudaGetSymbolAddress((void**)&wg1t, g_wg1t);
    cudaGetSymbolAddress((void**)&wg2t, g_wg2t);

    cudaFuncSetAttribute(hgemm, cudaFuncAttributeMaxDynamicSharedMemorySize, HG_SMEM);

    // 1: fused prep (transposes + x->half + f/gamma projections)
    k_prep<<<8576, dim3(32, 8)>>>(x, Wq, Wk, Wv, Wo, Wg1, Wg2, Wf, Wgamma,
                                  wqkvt, wot, wg1t, wg2t, xh, lam, gam);
    // 2: fused QKV GEMM
    hgemm<<<dim3(24, 32), 256, HG_SMEM>>>(xh, wqkvt, qkv, QSTR, DDIM, 1, 0);
    // 3: g1 = x @ Wg1 (half out)
    hgemm<<<dim3(1, 32), 256, HG_SMEM>>>(xh, wg1t, g1h, 64, DDIM, 0, 1);
    // 4: delta-rule scan (profiled slot)
    k_scan<<<128, 64>>>(qkv, lam, gam, attn);
    // 5: gate = sigmoid(g1 @ Wg2)
    hgemm<<<dim3(8, 32), 256, HG_SMEM>>>(g1h, wg2t, gate, DDIM, 64, 2, 0);
    // 6: gated LayerNorm -> half
    k_ln<<<MTOK, 256>>>(attn, gate, nw, normedh);
    // 7: out = normed @ Wo
    hgemm<<<dim3(8, 32), 256, HG_SMEM>>>(normedh, wot, out, DDIM, DDIM, 0, 0);
}

// round 9
// speedup vs baseline: 1.0678x; 1.0678x over previous
#include <cuda_runtime.h>
#include <cuda_fp16.h>
#include <math.h>
#include <stdint.h>

#define MTOK 4096   // B*N
#define DDIM 1024
#define NHEAD 16
#define SEQ 2048
#define QSTR 3072   // fused qkv row stride

// ---------------- scratch (device globals; no allocs allowed) ----------------
static __device__ float g_qkv[MTOK * QSTR];      // [q | k | v] fused
static __device__ float g_attn[MTOK * DDIM];
static __device__ float g_gate[MTOK * DDIM];
static __device__ float g_lam[MTOK * NHEAD];
static __device__ float g_gam[MTOK * NHEAD];
static __device__ __half g_xh[MTOK * DDIM];
static __device__ __half g_g1h[MTOK * 64];
static __device__ __half g_normedh[MTOK * DDIM];
static __device__ __half g_wqkvt[3 * DDIM * DDIM];
static __device__ __half g_wot[DDIM * DDIM];
static __device__ __half g_wg1t[64 * DDIM];
static __device__ __half g_wg2t[DDIM * 64];

__device__ __forceinline__ uint32_t smem_u32(const void* p) {
    uint32_t a;
    asm("{ .reg .u64 t; cvta.to.shared.u64 t, %1; cvt.u32.u64 %0, t; }" : "=r"(a) : "l"(p));
    return a;
}
__device__ __forceinline__ void cp16(uint32_t dst, const void* src, int valid) {
    int sz = valid ? 16 : 0;
    asm volatile("cp.async.cg.shared.global [%0], [%1], 16, %2;" :: "r"(dst), "l"(src), "r"(sz));
}
__device__ __forceinline__ void cp4(uint32_t dst, const void* src) {
    asm volatile("cp.async.ca.shared.global [%0], [%1], 4;" :: "r"(dst), "l"(src));
}

// ---- packed f32x2 helpers (sm_100+ PTX) ----
typedef unsigned long long ull;
__device__ __forceinline__ ull d_fma2(ull a, ull b, ull c) {
    ull r; asm("fma.rn.f32x2 %0,%1,%2,%3;" : "=l"(r) : "l"(a), "l"(b), "l"(c)); return r;
}
__device__ __forceinline__ ull d_mul2(ull a, ull b) {
    ull r; asm("mul.rn.f32x2 %0,%1,%2;" : "=l"(r) : "l"(a), "l"(b)); return r;
}
__device__ __forceinline__ ull d_add2(ull a, ull b) {
    ull r; asm("add.rn.f32x2 %0,%1,%2;" : "=l"(r) : "l"(a), "l"(b)); return r;
}
__device__ __forceinline__ ull d_pack(float lo, float hi) {
    ull r; asm("mov.b64 %0,{%1,%2};" : "=l"(r) : "f"(lo), "f"(hi)); return r;
}
__device__ __forceinline__ float d_hadd(ull p) {
    float lo, hi; asm("mov.b64 {%0,%1},%2;" : "=f"(lo), "=f"(hi) : "l"(p)); return lo + hi;
}

// ================= fp16 tensor-core GEMM: C = act(A @ Bt^T) =================
// Tile 128x128, K-tile 32, 4-stage cp.async (2-ahead), 2 CTAs/SM.
#define ROWB 80
#define STAGEB (128 * ROWB * 2)          // 20480
#define HG_SMEM (4 * STAGEB)             // 81920

__global__ __launch_bounds__(256, 2)
void hgemm(const __half* __restrict__ A, const __half* __restrict__ Bt,
           void* __restrict__ Cout, int Ntot, int K, int act, int outHalf)
{
    extern __shared__ __align__(128) char smem[];
    const uint32_t sb = smem_u32(smem);
    const int tid = threadIdx.x, lane = tid & 31, warp = tid >> 5;
    const int wm = warp >> 2, wn = warp & 3;
    const int g = lane >> 2, tig = lane & 3;
    const int m0 = blockIdx.y * 128, n0 = blockIdx.x * 128;
    const int NC = K >> 5;

    float acc[4][4][4];
#pragma unroll
    for (int mt = 0; mt < 4; ++mt)
#pragma unroll
        for (int nt = 0; nt < 4; ++nt)
#pragma unroll
            for (int j = 0; j < 4; ++j) acc[mt][nt][j] = 0.f;

#define LOAD_TILE(kt, ss) do { \
    uint32_t aB = sb + (ss) * STAGEB; \
    uint32_t bB = aB + 128 * ROWB; \
    _Pragma("unroll") \
    for (int i = 0; i < 2; ++i) { \
        int id = tid + i * 256; \
        int r = id >> 2, c = id & 3; \
        cp16(aB + r * ROWB + c * 16, A + (size_t)(m0 + r) * K + (kt) * 32 + c * 8, 1); \
        int nr = n0 + r; int ok = nr < Ntot; int nrc = ok ? nr : 0; \
        cp16(bB + r * ROWB + c * 16, Bt + (size_t)nrc * K + (kt) * 32 + c * 8, ok); \
    } \
} while (0)

#pragma unroll
    for (int p = 0; p < 3; ++p) {
        if (p < NC) LOAD_TILE(p, p);
        asm volatile("cp.async.commit_group;" ::: "memory");
    }

    for (int kt = 0; kt < NC; ++kt) {
        asm volatile("cp.async.wait_group 2;" ::: "memory");
        __syncthreads();
        int ln = kt + 3;
        if (ln < NC) LOAD_TILE(ln, ln & 3);
        asm volatile("cp.async.commit_group;" ::: "memory");

        uint32_t aB = sb + (kt & 3) * STAGEB;
        uint32_t bB = aB + 128 * ROWB;
#pragma unroll
        for (int s = 0; s < 2; ++s) {
            uint32_t af[4][4], bf[4][2];
#pragma unroll
            for (int mt = 0; mt < 4; ++mt) {
                uint32_t addr = aB + (wm * 64 + mt * 16 + (lane & 15)) * ROWB
                              + (2 * s + (lane >> 4)) * 16;
                asm volatile("ldmatrix.sync.aligned.m8n8.x4.shared.b16 {%0,%1,%2,%3}, [%4];"
                    : "=r"(af[mt][0]), "=r"(af[mt][1]), "=r"(af[mt][2]), "=r"(af[mt][3])
                    : "r"(addr));
            }
#pragma unroll
            for (int nt = 0; nt < 4; ++nt) {
                uint32_t addr = bB + (wn * 32 + nt * 8 + (lane & 7)) * ROWB
                              + (2 * s + ((lane >> 3) & 1)) * 16;
                asm volatile("ldmatrix.sync.aligned.m8n8.x2.shared.b16 {%0,%1}, [%2];"
                    : "=r"(bf[nt][0]), "=r"(bf[nt][1]) : "r"(addr));
            }
#pragma unroll
            for (int mt = 0; mt < 4; ++mt)
#pragma unroll
                for (int nt = 0; nt < 4; ++nt) {
                    asm volatile(
                        "mma.sync.aligned.m16n8k16.row.col.f32.f16.f16.f32 "
                        "{%0,%1,%2,%3}, {%4,%5,%6,%7}, {%8,%9}, {%0,%1,%2,%3};"
                        : "+f"(acc[mt][nt][0]), "+f"(acc[mt][nt][1]),
                          "+f"(acc[mt][nt][2]), "+f"(acc[mt][nt][3])
                        : "r"(af[mt][0]), "r"(af[mt][1]), "r"(af[mt][2]), "r"(af[mt][3]),
                          "r"(bf[nt][0]), "r"(bf[nt][1]));
                }
        }
        __syncthreads();
    }
#undef LOAD_TILE

    float* Cf = (float*)Cout;
    __half* Ch = (__half*)Cout;
#pragma unroll
    for (int mt = 0; mt < 4; ++mt) {
        int row = m0 + wm * 64 + mt * 16 + g;
#pragma unroll
        for (int nt = 0; nt < 4; ++nt) {
            int col = n0 + wn * 32 + nt * 8 + tig * 2;
            if (col < Ntot) {
                float c0 = acc[mt][nt][0], c1 = acc[mt][nt][1];
                float c2 = acc[mt][nt][2], c3 = acc[mt][nt][3];
                if (act == 1) {
                    c0 = c0 / (1.f + expf(-c0)); c1 = c1 / (1.f + expf(-c1));
                    c2 = c2 / (1.f + expf(-c2)); c3 = c3 / (1.f + expf(-c3));
                } else if (act == 2) {
                    c0 = 1.f / (1.f + expf(-c0)); c1 = 1.f / (1.f + expf(-c1));
                    c2 = 1.f / (1.f + expf(-c2)); c3 = 1.f / (1.f + expf(-c3));
                }
                if (outHalf) {
                    *(__half2*)&Ch[(size_t)row * Ntot + col]       = __floats2half2_rn(c0, c1);
                    *(__half2*)&Ch[(size_t)(row + 8) * Ntot + col] = __floats2half2_rn(c2, c3);
                } else {
                    *(float2*)&Cf[(size_t)row * Ntot + col]       = make_float2(c0, c1);
                    *(float2*)&Cf[(size_t)(row + 8) * Ntot + col] = make_float2(c2, c3);
                }
            }
        }
    }
}

// ================= fused prep: transposes + f2h + fgamma in ONE launch =================
__global__ void k_prep(const float* __restrict__ x,
                       const float* __restrict__ Wq, const float* __restrict__ Wk,
                       const float* __restrict__ Wv, const float* __restrict__ Wo,
                       const float* __restrict__ Wg1, const float* __restrict__ Wg2,
                       const float* __restrict__ Wf, const float* __restrict__ Wgm,
                       __half* __restrict__ wqkvt, __half* __restrict__ wot,
                       __half* __restrict__ wg1t, __half* __restrict__ wg2t,
                       __half* __restrict__ xh,
                       float* __restrict__ lam, float* __restrict__ gam)
{
    int blk = blockIdx.x;
    int tid = threadIdx.y * 32 + threadIdx.x;
    if (blk < 4224) {
        __shared__ float t[32][33];
        const float* S; __half* D; int R, C, tile;
        if (blk < 3072) {
            int seg = blk >> 10; tile = blk & 1023;
            S = (seg == 0) ? Wq : (seg == 1) ? Wk : Wv;
            D = wqkvt + (size_t)seg * DDIM * DDIM; R = DDIM; C = DDIM;
        } else if (blk < 4096) { tile = blk - 3072; S = Wo;  D = wot;  R = DDIM; C = DDIM; }
        else if (blk < 4160)   { tile = blk - 4096; S = Wg1; D = wg1t; R = DDIM; C = 64; }
        else                   { tile = blk - 4160; S = Wg2; D = wg2t; R = 64;   C = DDIM; }
        int tiles_x = C >> 5;
        int c0 = (tile % tiles_x) * 32, r0 = (tile / tiles_x) * 32;
        int xq = threadIdx.x, y = threadIdx.y;
#pragma unroll
        for (int i = 0; i < 32; i += 8) t[y + i][xq] = S[(size_t)(r0 + y + i) * C + c0 + xq];
        __syncthreads();
#pragma unroll
        for (int i = 0; i < 32; i += 8)
            D[(size_t)(c0 + y + i) * R + r0 + xq] = __float2half_rn(t[xq][y + i]);
    } else if (blk < 8320) {
        int i = ((blk - 4224) * 256 + tid) * 4;
        float4 f = *(const float4*)&x[i];
        *(__half2*)&xh[i]     = __floats2half2_rn(f.x, f.y);
        *(__half2*)&xh[i + 2] = __floats2half2_rn(f.z, f.w);
    } else {
        __shared__ float xs[16][33];
        __shared__ float Ws[32][32];
        int t0 = (blk - 8320) * 16;
        int c = tid & 31, tg = tid >> 5;
        float acc[2] = {0.f, 0.f};
        for (int k0 = 0; k0 < DDIM; k0 += 32) {
            __syncthreads();
#pragma unroll
            for (int i = 0; i < 2; ++i) {
                int idx = tid + i * 256;
                int tt = idx >> 5, kk = idx & 31;
                xs[tt][kk] = x[(size_t)(t0 + tt) * DDIM + k0 + kk];
            }
#pragma unroll
            for (int i = 0; i < 4; ++i) {
                int idx = tid + i * 256;
                int kr = idx >> 5, col = idx & 31;
                Ws[kr][col] = (col < 16) ? Wf[(k0 + kr) * NHEAD + col]
                                         : Wgm[(k0 + kr) * NHEAD + (col - 16)];
            }
            __syncthreads();
#pragma unroll 8
            for (int kk = 0; kk < 32; ++kk) {
                float w = Ws[kk][c];
                acc[0] = fmaf(xs[tg * 2][kk], w, acc[0]);
                acc[1] = fmaf(xs[tg * 2 + 1][kk], w, acc[1]);
            }
        }
#pragma unroll
        for (int i = 0; i < 2; ++i) {
            int t = t0 + tg * 2 + i;
            float sg = 1.f / (1.f + expf(-acc[i]));
            if (c < 16) lam[t * NHEAD + c] = sg;
            else        gam[t * NHEAD + (c - 16)] = -sg;
        }
    }
}

// ================= delta-rule scan (fused l2norm, packed f32x2 math) =================
// 128 blocks = 32 (b,h) x 4 quarters; 128 thr = 16 cols x 8 subs; 8 state = 4 f32x2.
// e = k.s ; u = (l^2*gam*invn)*e + v ; s' = l*s + k*(invn*u) ; o = q.s'
__global__ __launch_bounds__(128)
void k_scan(const float* __restrict__ qkv, const float* __restrict__ lamA,
            const float* __restrict__ gamA, float* __restrict__ o)
{
    __shared__ __align__(16) float qs[2][16][64];
    __shared__ __align__(16) float ks[2][16][64];
    __shared__ __align__(16) float vs[2][16][16];
    __shared__ float lmS[2][16], gmS[2][16], f1S[2][16], inS[2][16];

    const int blk = blockIdx.x;           // 0..127
    const int bh = blk >> 2, quarter = blk & 3;
    const int b = bh >> 4, h = bh & 15;
    const int tid = threadIdx.x;          // 0..127
    const int col = tid >> 3;             // 0..15
    const int sub = tid & 7;              // 0..7
    const int tok0 = b * SEQ;
    const int hoff = h * 64;

    const uint32_t qsB = smem_u32(&qs[0][0][0]);
    const uint32_t ksB = smem_u32(&ks[0][0][0]);
    const uint32_t vsB = smem_u32(&vs[0][0][0]);
    const uint32_t lmB = smem_u32(&lmS[0][0]);
    const uint32_t gmB = smem_u32(&gmS[0][0]);

#define SC_LOAD(stg, buf) do { \
    int tb_ = tok0 + (stg) * 16; \
    _Pragma("unroll") \
    for (int i = 0; i < 2; ++i) { \
        int idx = tid + i * 128; \
        int tt = idx >> 4, c4 = idx & 15; \
        uint32_t so = (uint32_t)(((buf) * 16 + tt) * 64 + c4 * 4) * 4; \
        const float* qrow = qkv + (size_t)(tb_ + tt) * QSTR + hoff + c4 * 4; \
        cp16(qsB + so, qrow, 1); \
        cp16(ksB + so, qrow + DDIM, 1); \
    } \
    if (tid < 64) { \
        int tt = tid >> 2, c4 = tid & 3; \
        uint32_t so = (uint32_t)(((buf) * 16 + tt) * 16 + c4 * 4) * 4; \
        cp16(vsB + so, qkv + (size_t)(tb_ + tt) * QSTR + 2 * DDIM + hoff + quarter * 16 + c4 * 4, 1); \
    } \
    if (tid < 16) \
        cp4(lmB + (uint32_t)((buf) * 16 + tid) * 4, lamA + (size_t)(tb_ + tid) * NHEAD + h); \
    else if (tid < 32) \
        cp4(gmB + (uint32_t)((buf) * 16 + tid - 16) * 4, gamA + (size_t)(tb_ + tid - 16) * NHEAD + h); \
} while (0)

#define SC_PRE(buf) do { \
    int tt_ = tid >> 3, p_ = tid & 7; \
    const float* kr = &ks[buf][tt_][p_ * 8]; \
    float4 pa = *(const float4*)kr, pb = *(const float4*)(kr + 4); \
    float ssum = pa.x*pa.x + pa.y*pa.y + pa.z*pa.z + pa.w*pa.w \
               + pb.x*pb.x + pb.y*pb.y + pb.z*pb.z + pb.w*pb.w; \
    ssum += __shfl_xor_sync(0xffffffffu, ssum, 1); \
    ssum += __shfl_xor_sync(0xffffffffu, ssum, 2); \
    ssum += __shfl_xor_sync(0xffffffffu, ssum, 4); \
    if (p_ == 0) { \
        float inv_ = 1.f / fmaxf(sqrtf(ssum), 1e-12f); \
        float l_ = lmS[buf][tt_]; \
        float c_ = gmS[buf][tt_] * l_; \
        inS[buf][tt_] = inv_; \
        f1S[buf][tt_] = l_ * c_ * inv_; \
    } \
} while (0)

    ull s0 = 0, s1 = 0, s2 = 0, s3 = 0;   // packed (0.f,0.f) pairs

    SC_LOAD(0, 0);
    asm volatile("cp.async.commit_group;" ::: "memory");
    asm volatile("cp.async.wait_group 0;" ::: "memory");
    __syncthreads();
    SC_PRE(0);
    __syncthreads();

    const int NT = SEQ / 16;
    for (int st = 0; st < NT; ++st) {
        const int buf = st & 1;
        if (st + 1 < NT) SC_LOAD(st + 1, buf ^ 1);
        asm volatile("cp.async.commit_group;" ::: "memory");

        const int tb = tok0 + st * 16;
#pragma unroll
        for (int tt = 0; tt < 16; ++tt) {
            float l = lmS[buf][tt];
            float f1 = f1S[buf][tt];
            float inv = inS[buf][tt];
            float cv = vs[buf][tt][col];
            float4 kv0 = *(const float4*)&ks[buf][tt][sub * 8];
            float4 kv1 = *(const float4*)&ks[buf][tt][sub * 8 + 4];
            ull ka = d_pack(kv0.x, kv0.y), kb = d_pack(kv0.z, kv0.w);
            ull kc = d_pack(kv1.x, kv1.y), kd = d_pack(kv1.z, kv1.w);
            // e = k . s  (packed)
            ull e0 = d_mul2(ka, s0); e0 = d_fma2(kb, s1, e0);
            ull e1 = d_mul2(kc, s2); e1 = d_fma2(kd, s3, e1);
            float e = d_hadd(d_add2(e0, e1));
            e += __shfl_xor_sync(0xffffffffu, e, 1);
            e += __shfl_xor_sync(0xffffffffu, e, 2);
            e += __shfl_xor_sync(0xffffffffu, e, 4);
            float u = fmaf(f1, e, cv);
            float w = inv * u;
            ull w2 = d_pack(w, w), l2 = d_pack(l, l);
            s0 = d_fma2(ka, w2, d_mul2(l2, s0));
            s1 = d_fma2(kb, w2, d_mul2(l2, s1));
            s2 = d_fma2(kc, w2, d_mul2(l2, s2));
            s3 = d_fma2(kd, w2, d_mul2(l2, s3));
            float4 qv0 = *(const float4*)&qs[buf][tt][sub * 8];
            float4 qv1 = *(const float4*)&qs[buf][tt][sub * 8 + 4];
            ull o0 = d_mul2(d_pack(qv0.x, qv0.y), s0);
            o0 = d_fma2(d_pack(qv0.z, qv0.w), s1, o0);
            ull o1 = d_mul2(d_pack(qv1.x, qv1.y), s2);
            o1 = d_fma2(d_pack(qv1.z, qv1.w), s3, o1);
            float op = d_hadd(d_add2(o0, o1));
            op += __shfl_xor_sync(0xffffffffu, op, 1);
            op += __shfl_xor_sync(0xffffffffu, op, 2);
            op += __shfl_xor_sync(0xffffffffu, op, 4);
            if (sub == 0)
                o[(size_t)(tb + tt) * DDIM + hoff + quarter * 16 + col] = op;
        }
        asm volatile("cp.async.wait_group 0;" ::: "memory");
        __syncthreads();
        if (st + 1 < NT) {
            SC_PRE(buf ^ 1);
            __syncthreads();
        }
    }
#undef SC_LOAD
#undef SC_PRE
}

// ================= gate-multiply + LayerNorm -> half =================
__global__ void k_ln(const float* __restrict__ attn, const float* __restrict__ gate,
                     const float* __restrict__ nw, __half* __restrict__ outh)
{
    __shared__ float red[32];
    int t = blockIdx.x;
    int tid = threadIdx.x;  // 256
    int lane = tid & 31, w = tid >> 5;
    float y[4];
    float sm = 0.f;
#pragma unroll
    for (int i = 0; i < 4; ++i) {
        int j = tid + i * 256;
        y[i] = attn[(size_t)t * DDIM + j] * gate[(size_t)t * DDIM + j];
        sm += y[i];
    }
#pragma unroll
    for (int o = 16; o; o >>= 1) sm += __shfl_xor_sync(0xffffffffu, sm, o);
    if (lane == 0) red[w] = sm;
    __syncthreads();
    if (w == 0) {
        float v2 = (lane < 8) ? red[lane] : 0.f;
#pragma unroll
        for (int o = 4; o; o >>= 1) v2 += __shfl_xor_sync(0xffffffffu, v2, o);
        if (lane == 0) red[0] = v2;
    }
    __syncthreads();
    float mu = red[0] * (1.f / DDIM);
    __syncthreads();
    float vsum = 0.f;
#pragma unroll
    for (int i = 0; i < 4; ++i) { float d = y[i] - mu; vsum += d * d; }
#pragma unroll
    for (int o = 16; o; o >>= 1) vsum += __shfl_xor_sync(0xffffffffu, vsum, o);
    if (lane == 0) red[w] = vsum;
    __syncthreads();
    if (w == 0) {
        float v2 = (lane < 8) ? red[lane] : 0.f;
#pragma unroll
        for (int o = 4; o; o >>= 1) v2 += __shfl_xor_sync(0xffffffffu, v2, o);
        if (lane == 0) red[0] = v2;
    }
    __syncthreads();
    float inv = rsqrtf(red[0] * (1.f / DDIM) + 1e-5f);
#pragma unroll
    for (int i = 0; i < 4; ++i) {
        int j = tid + i * 256;
        outh[(size_t)t * DDIM + j] = __float2half_rn((y[i] - mu) * inv * nw[j]);
    }
}

// ================= launch =================
extern "C" void kernel_launch(void* const* d_in, const int* in_sizes, int n_in,
                              void* d_out, int out_size)
{
    const float* x      = (const float*)d_in[0];
    const float* Wq     = (const float*)d_in[1];
    const float* Wk     = (const float*)d_in[2];
    const float* Wv     = (const float*)d_in[3];
    const float* Wgamma = (const float*)d_in[4];
    const float* Wf     = (const float*)d_in[5];
    const float* Wg1    = (const float*)d_in[6];
    const float* Wg2    = (const float*)d_in[7];
    const float* Wo     = (const float*)d_in[8];
    const float* nw     = (const float*)d_in[9];
    float* out = (float*)d_out;

    float *qkv, *attn, *gate, *lam, *gam;
    __half *xh, *g1h, *normedh, *wqkvt, *wot, *wg1t, *wg2t;
    cudaGetSymbolAddress((void**)&qkv, g_qkv);
    cudaGetSymbolAddress((void**)&attn, g_attn);
    cudaGetSymbolAddress((void**)&gate, g_gate);
    cudaGetSymbolAddress((void**)&lam, g_lam);
    cudaGetSymbolAddress((void**)&gam, g_gam);
    cudaGetSymbolAddress((void**)&xh, g_xh);
    cudaGetSymbolAddress((void**)&g1h, g_g1h);
    cudaGetSymbolAddress((void**)&normedh, g_normedh);
    cudaGetSymbolAddress((void**)&wqkvt, g_wqkvt);
    cudaGetSymbolAddress((void**)&wot, g_wot);
    cudaGetSymbolAddress((void**)&wg1t, g_wg1t);
    cudaGetSymbolAddress((void**)&wg2t, g_wg2t);

    cudaFuncSetAttribute(hgemm, cudaFuncAttributeMaxDynamicSharedMemorySize, HG_SMEM);

    // 1: fused prep (transposes + x->half + f/gamma projections)
    k_prep<<<8576, dim3(32, 8)>>>(x, Wq, Wk, Wv, Wo, Wg1, Wg2, Wf, Wgamma,
                                  wqkvt, wot, wg1t, wg2t, xh, lam, gam);
    // 2: fused QKV GEMM
    hgemm<<<dim3(24, 32), 256, HG_SMEM>>>(xh, wqkvt, qkv, QSTR, DDIM, 1, 0);
    // 3: g1 = x @ Wg1 (half out)
    hgemm<<<dim3(1, 32), 256, HG_SMEM>>>(xh, wg1t, g1h, 64, DDIM, 0, 1);
    // 4: delta-rule scan (profiled slot)
    k_scan<<<128, 128>>>(qkv, lam, gam, attn);
    // 5: gate = sigmoid(g1 @ Wg2)
    hgemm<<<dim3(8, 32), 256, HG_SMEM>>>(g1h, wg2t, gate, DDIM, 64, 2, 0);
    // 6: gated LayerNorm -> half
    k_ln<<<MTOK, 256>>>(attn, gate, nw, normedh);
    // 7: out = normed @ Wo
    hgemm<<<dim3(8, 32), 256, HG_SMEM>>>(normedh, wot, out, DDIM, DDIM, 0, 0);
}